// round 10
// baseline (speedup 1.0000x reference)
#include <cuda_runtime.h>
#include <math.h>
#include <stdint.h>

#define MAX_N   1024
#define EPS     1e-4f
#define ZCHUNK  32768          // bytes per bulk store
#define ZPER    4              // chunks per CTA
#define BANDS   4
#define CAP     12288          // per-band list capacity

// ---- scratch (__device__ globals; no allocation allowed) ----
__device__ float g_diag[MAX_N * 64];    // per-node sum of R^T R
__device__ float g_dis [MAX_N * 64];    // per-node D^{-1/2}
__device__ int   g_cnt [BANDS];         // per-band work counts
__device__ int   g_list[BANDS * CAP];   // per-band block-id lists

// ---- bucket output blocks (edge p -> id=p, diag v -> id=P+v) by i-band ----
__global__ void k_bucket(const int* __restrict__ E, int P, int n, int rpc) {
    int t = blockIdx.x * blockDim.x + threadIdx.x;
    if (t >= P + n) return;
    int i = (t < P) ? E[2 * t] : (t - P);
    int band = i / rpc;
    int idx = atomicAdd(&g_cnt[band], 1);
    if (idx < CAP) g_list[band * CAP + idx] = t;
}

// ---- zero one byte-range of the output via TMA bulk stores ----
__global__ void k_zero_tma(char* __restrict__ out, size_t total) {
    __shared__ __align__(128) char buf[ZCHUNK];
    float4* b4 = (float4*)buf;
    for (int t = threadIdx.x; t < ZCHUNK / 16; t += blockDim.x)
        b4[t] = make_float4(0.f, 0.f, 0.f, 0.f);
    __syncthreads();
    asm volatile("fence.proxy.async.shared::cta;" ::: "memory");
    if (threadIdx.x == 0) {
        uint32_t saddr;
        asm("{ .reg .u64 t; cvta.to.shared.u64 t, %1; cvt.u32.u64 %0, t; }"
            : "=r"(saddr) : "l"(buf));
        size_t base = (size_t)blockIdx.x * (ZPER * (size_t)ZCHUNK);
#pragma unroll
        for (int k = 0; k < ZPER; k++) {
            size_t off = base + (size_t)k * ZCHUNK;
            if (off >= total) break;
            size_t rem = total - off;
            unsigned len = (unsigned)(rem >= ZCHUNK ? ZCHUNK : rem);
            asm volatile(
                "cp.async.bulk.global.shared::cta.bulk_group [%0], [%1], %2;"
                :: "l"(out + off), "r"(saddr), "r"(len) : "memory");
        }
        asm volatile("cp.async.bulk.commit_group;" ::: "memory");
        asm volatile("cp.async.bulk.wait_group 0;" ::: "memory");
    }
}

// ---- per-edge FtF = R^T R, atomically accumulated into g_diag[i] ----
__global__ void k_ftf(const float* __restrict__ R, const int* __restrict__ E, int P) {
    int gid = blockIdx.x * blockDim.x + threadIdx.x;
    if (gid >= P * 64) return;
    int p = gid >> 6;
    int e = gid & 63;
    int r = e >> 3, c = e & 7;
    int i = E[2 * p];
    const float* Rp = R + (size_t)p * 64;
    float v = 0.f;
#pragma unroll
    for (int k = 0; k < 8; k++) v += Rp[k * 8 + r] * Rp[k * 8 + c];
    atomicAdd(&g_diag[i * 64 + e], v);
}

// ---- per-node D^{-1/2} via coupled Newton-Schulz; 4 nodes per 256-thread CTA ----
__global__ void k_ns(int n) {
    __shared__ float Y[4][64], Z[4][64], G[4][64], red[4][64];
    int sub = threadIdx.x >> 6;     // node within CTA
    int t   = threadIdx.x & 63;
    int v   = blockIdx.x * 4 + sub;
    int vc  = (v < n) ? v : (n - 1);
    int r = t >> 3, c = t & 7;

    float a = g_diag[vc * 64 + r * 8 + c];
    float b = g_diag[vc * 64 + c * 8 + r];
    float d = 0.5f * (a + b) + ((r == c) ? EPS : 0.f);

    red[sub][t] = d * d;
    __syncthreads();
    if (t < 32) red[sub][t] += red[sub][t + 32];
    __syncthreads();
    if (t < 16) red[sub][t] += red[sub][t + 16];
    __syncthreads();
    if (t < 8)  red[sub][t] += red[sub][t + 8];
    __syncthreads();
    if (t < 4)  red[sub][t] += red[sub][t + 4];
    __syncthreads();
    if (t < 2)  red[sub][t] += red[sub][t + 2];
    __syncthreads();
    if (t == 0) red[sub][0] += red[sub][1];
    __syncthreads();
    float s = sqrtf(red[sub][0]);
    float inv_s = 1.f / s;

    Y[sub][t] = d * inv_s;
    Z[sub][t] = (r == c) ? 1.f : 0.f;
    __syncthreads();

    for (int it = 0; it < 24; it++) {
        float acc = 0.f;
#pragma unroll
        for (int k = 0; k < 8; k++) acc += Z[sub][r * 8 + k] * Y[sub][k * 8 + c];
        float g = ((r == c) ? 1.5f : 0.f) - 0.5f * acc;
        __syncthreads();
        G[sub][t] = g;
        __syncthreads();
        float ny = 0.f, nz = 0.f;
#pragma unroll
        for (int k = 0; k < 8; k++) {
            ny += Y[sub][r * 8 + k] * G[sub][k * 8 + c];
            nz += G[sub][r * 8 + k] * Z[sub][k * 8 + c];
        }
        __syncthreads();
        Y[sub][t] = ny;
        Z[sub][t] = nz;
        __syncthreads();
    }

    if (v < n) g_dis[v * 64 + t] = Z[sub][t] * rsqrtf(s);
}

// ---- k_blocks: 256 threads/CTA, 4 listed output blocks per CTA (one band).
//      reverse edge of p is (p +- P/2) by construction. ----
__global__ void k_blocks(const float* __restrict__ R, const int* __restrict__ E,
                         const float* __restrict__ L1, float* __restrict__ out,
                         int P, int n, int band) {
    __shared__ float M1T[4][64], M2[4][64], Di[4][64], Dj[4][64], B[4][64], T[4][64];
    int sub = threadIdx.x >> 6;
    int t   = threadIdx.x & 63;
    int idx = blockIdx.x * 4 + sub;
    int cnt = g_cnt[band];
    bool valid = (idx < cnt);
    int b = valid ? g_list[band * CAP + idx] : 0;
    bool is_edge = valid && (b < P);
    int i = 0, j = 0;
    float sgn = 0.f;

    if (valid) {
        if (is_edge) {
            int2 e = ((const int2*)E)[b];
            i = e.x; j = e.y;
        } else {
            i = j = b - P;
        }
    }

    int r = t >> 3, c = t & 7;
    int g = t & 15, sel = t >> 4;

    if (valid) {
        if (is_edge) {
            int half = P >> 1;
            int rev = (b < half) ? (b + half) : (b - half);
            float l = L1[(size_t)i * n + j];
            sgn = (l > 0.f) ? 1.f : ((l < 0.f) ? -1.f : 0.f);
            if (sel == 0) {
                float4 v = ((const float4*)(R + (size_t)rev * 64))[g];
                int row = g >> 1, c0 = (g & 1) * 4;
                M1T[sub][(c0 + 0) * 8 + row] = v.x;
                M1T[sub][(c0 + 1) * 8 + row] = v.y;
                M1T[sub][(c0 + 2) * 8 + row] = v.z;
                M1T[sub][(c0 + 3) * 8 + row] = v.w;
            } else if (sel == 1) {
                ((float4*)M2[sub])[g] = ((const float4*)(R + (size_t)b * 64))[g];
            } else if (sel == 2) {
                ((float4*)Di[sub])[g] = ((const float4*)(g_dis + (size_t)i * 64))[g];
            } else {
                ((float4*)Dj[sub])[g] = ((const float4*)(g_dis + (size_t)j * 64))[g];
            }
        } else {
            if (sel == 0) {
                ((float4*)B[sub])[g]  = ((const float4*)(g_diag + (size_t)i * 64))[g];
            } else if (sel == 2) {
                ((float4*)Di[sub])[g] = ((const float4*)(g_dis + (size_t)i * 64))[g];
            } else if (sel == 3) {
                ((float4*)Dj[sub])[g] = ((const float4*)(g_dis + (size_t)i * 64))[g];
            }
        }
    }
    __syncthreads();

    if (is_edge) {
        float4 a0 = ((const float4*)(M1T[sub] + r * 8))[0];
        float4 a1 = ((const float4*)(M1T[sub] + r * 8))[1];
        const float* Bc = M2[sub] + c;
        float s = a0.x * Bc[0]  + a0.y * Bc[8]  + a0.z * Bc[16] + a0.w * Bc[24]
                + a1.x * Bc[32] + a1.y * Bc[40] + a1.z * Bc[48] + a1.w * Bc[56];
        B[sub][t] = -sgn * s;
    }
    __syncthreads();
    if (valid) {
        float4 a0 = ((const float4*)(Di[sub] + r * 8))[0];
        float4 a1 = ((const float4*)(Di[sub] + r * 8))[1];
        const float* Bc = B[sub] + c;
        float s = a0.x * Bc[0]  + a0.y * Bc[8]  + a0.z * Bc[16] + a0.w * Bc[24]
                + a1.x * Bc[32] + a1.y * Bc[40] + a1.z * Bc[48] + a1.w * Bc[56];
        T[sub][t] = s;
    }
    __syncthreads();
    if (valid) {
        float4 a0 = ((const float4*)(T[sub] + r * 8))[0];
        float4 a1 = ((const float4*)(T[sub] + r * 8))[1];
        const float* Bc = Dj[sub] + c;
        float s = a0.x * Bc[0]  + a0.y * Bc[8]  + a0.z * Bc[16] + a0.w * Bc[24]
                + a1.x * Bc[32] + a1.y * Bc[40] + a1.z * Bc[48] + a1.w * Bc[56];
        size_t nd = (size_t)n * 8;
        out[((size_t)i * 8 + r) * nd + (size_t)j * 8 + c] = s;
    }
}

extern "C" void kernel_launch(void* const* d_in, const int* in_sizes, int n_in,
                              void* d_out, int out_size) {
    const float* R  = (const float*)d_in[0];  // (P, 8, 8)
    const int*   E  = (const int*)  d_in[1];  // (P, 2)
    const float* L1 = (const float*)d_in[3];  // (n, n)

    int P = in_sizes[1] / 2;
    int n = (int)(sqrt((double)in_sizes[3]) + 0.5);

    // one-time host-side resources (streams/events are NOT device memory)
    static bool inited = false;
    static cudaStream_t side;
    static cudaEvent_t ev_fork, ev_z[BANDS], ev_join;
    static void* diag_ptr;
    static void* cnt_ptr;
    if (!inited) {
        cudaStreamCreateWithFlags(&side, cudaStreamNonBlocking);
        cudaEventCreateWithFlags(&ev_fork, cudaEventDisableTiming);
        for (int c = 0; c < BANDS; c++)
            cudaEventCreateWithFlags(&ev_z[c], cudaEventDisableTiming);
        cudaEventCreateWithFlags(&ev_join, cudaEventDisableTiming);
        cudaGetSymbolAddress(&diag_ptr, g_diag);
        cudaGetSymbolAddress(&cnt_ptr, g_cnt);
        inited = true;
    }

    int rpc = (n + BANDS - 1) / BANDS;     // node rows per band
    size_t total = (size_t)out_size * sizeof(float);
    size_t band_bytes = (size_t)rpc * 8 * (size_t)n * 8 * sizeof(float);
    size_t per_cta = (size_t)ZPER * ZCHUNK;

    // side stream: prefix chain (bucket + ftf + ns), forked at t=0
    cudaEventRecord(ev_fork, 0);
    cudaStreamWaitEvent(side, ev_fork, 0);
    cudaMemsetAsync(diag_ptr, 0, (size_t)n * 64 * sizeof(float), side);
    cudaMemsetAsync(cnt_ptr, 0, BANDS * sizeof(int), side);
    k_bucket<<<(P + n + 255) / 256, 256, 0, side>>>(E, P, n, rpc);
    k_ftf<<<(P * 64 + 255) / 256, 256, 0, side>>>(R, E, P);
    k_ns<<<(n + 3) / 4, 256, 0, side>>>(n);

    // main stream: banded TMA zero; record event after each band
    for (int c = 0; c < BANDS; c++) {
        size_t off = (size_t)c * band_bytes;
        if (off < total) {
            size_t len = band_bytes;
            if (off + len > total) len = total - off;
            int zgrid = (int)((len + per_cta - 1) / per_cta);
            k_zero_tma<<<zgrid, 128>>>((char*)d_out + off, len);
        }
        cudaEventRecord(ev_z[c], 0);
    }

    // side stream: pipelined block writer (after chain, per-band zero gates)
    int grid = (CAP + 3) / 4;
    for (int c = 0; c < BANDS; c++) {
        if (c * rpc >= n) break;
        cudaStreamWaitEvent(side, ev_z[c], 0);
        k_blocks<<<grid, 256, 0, side>>>(R, E, L1, (float*)d_out, P, n, c);
    }

    // join: side stream's writes complete before launch is done
    cudaEventRecord(ev_join, side);
    cudaStreamWaitEvent(0, ev_join, 0);
}

// round 11
// speedup vs baseline: 1.1725x; 1.1725x over previous
#include <cuda_runtime.h>
#include <math.h>
#include <stdint.h>

#define MAX_N  1024
#define MAX_P  33792           // P + n upper bound (32768 + 1024)
#define EPS    1e-4f
#define ZCHUNK 32768           // bytes per bulk store
#define ZPER   4               // chunks per CTA

// ---- scratch (__device__ globals; no allocation allowed) ----
__device__ float g_diag [MAX_N * 64];   // per-node sum of R^T R
__device__ float g_dis  [MAX_N * 64];   // per-node D^{-1/2}
__device__ float g_stage[MAX_P * 64];   // staged nonzero 8x8 blocks (8.6MB)

// ---- zero one byte-range of the output via TMA bulk stores ----
__global__ void k_zero_tma(char* __restrict__ out, size_t total) {
    __shared__ __align__(128) char buf[ZCHUNK];
    float4* b4 = (float4*)buf;
    for (int t = threadIdx.x; t < ZCHUNK / 16; t += blockDim.x)
        b4[t] = make_float4(0.f, 0.f, 0.f, 0.f);
    __syncthreads();
    asm volatile("fence.proxy.async.shared::cta;" ::: "memory");
    if (threadIdx.x == 0) {
        uint32_t saddr;
        asm("{ .reg .u64 t; cvta.to.shared.u64 t, %1; cvt.u32.u64 %0, t; }"
            : "=r"(saddr) : "l"(buf));
        size_t base = (size_t)blockIdx.x * (ZPER * (size_t)ZCHUNK);
#pragma unroll
        for (int k = 0; k < ZPER; k++) {
            size_t off = base + (size_t)k * ZCHUNK;
            if (off >= total) break;
            size_t rem = total - off;
            unsigned len = (unsigned)(rem >= ZCHUNK ? ZCHUNK : rem);
            asm volatile(
                "cp.async.bulk.global.shared::cta.bulk_group [%0], [%1], %2;"
                :: "l"(out + off), "r"(saddr), "r"(len) : "memory");
        }
        asm volatile("cp.async.bulk.commit_group;" ::: "memory");
        asm volatile("cp.async.bulk.wait_group 0;" ::: "memory");
    }
}

// ---- per-edge FtF = R^T R, atomically accumulated into g_diag[i] ----
__global__ void k_ftf(const float* __restrict__ R, const int* __restrict__ E, int P) {
    int gid = blockIdx.x * blockDim.x + threadIdx.x;
    if (gid >= P * 64) return;
    int p = gid >> 6;
    int e = gid & 63;
    int r = e >> 3, c = e & 7;
    int i = E[2 * p];
    const float* Rp = R + (size_t)p * 64;
    float v = 0.f;
#pragma unroll
    for (int k = 0; k < 8; k++) v += Rp[k * 8 + r] * Rp[k * 8 + c];
    atomicAdd(&g_diag[i * 64 + e], v);
}

// ---- per-node D^{-1/2} via coupled Newton-Schulz; 4 nodes per 256-thread CTA ----
__global__ void k_ns(int n) {
    __shared__ float Y[4][64], Z[4][64], G[4][64], red[4][64];
    int sub = threadIdx.x >> 6;
    int t   = threadIdx.x & 63;
    int v   = blockIdx.x * 4 + sub;
    int vc  = (v < n) ? v : (n - 1);
    int r = t >> 3, c = t & 7;

    float a = g_diag[vc * 64 + r * 8 + c];
    float b = g_diag[vc * 64 + c * 8 + r];
    float d = 0.5f * (a + b) + ((r == c) ? EPS : 0.f);

    red[sub][t] = d * d;
    __syncthreads();
    if (t < 32) red[sub][t] += red[sub][t + 32];
    __syncthreads();
    if (t < 16) red[sub][t] += red[sub][t + 16];
    __syncthreads();
    if (t < 8)  red[sub][t] += red[sub][t + 8];
    __syncthreads();
    if (t < 4)  red[sub][t] += red[sub][t + 4];
    __syncthreads();
    if (t < 2)  red[sub][t] += red[sub][t + 2];
    __syncthreads();
    if (t == 0) red[sub][0] += red[sub][1];
    __syncthreads();
    float s = sqrtf(red[sub][0]);
    float inv_s = 1.f / s;

    Y[sub][t] = d * inv_s;
    Z[sub][t] = (r == c) ? 1.f : 0.f;
    __syncthreads();

    for (int it = 0; it < 24; it++) {
        float acc = 0.f;
#pragma unroll
        for (int k = 0; k < 8; k++) acc += Z[sub][r * 8 + k] * Y[sub][k * 8 + c];
        float g = ((r == c) ? 1.5f : 0.f) - 0.5f * acc;
        __syncthreads();
        G[sub][t] = g;
        __syncthreads();
        float ny = 0.f, nz = 0.f;
#pragma unroll
        for (int k = 0; k < 8; k++) {
            ny += Y[sub][r * 8 + k] * G[sub][k * 8 + c];
            nz += G[sub][r * 8 + k] * Z[sub][k * 8 + c];
        }
        __syncthreads();
        Y[sub][t] = ny;
        Z[sub][t] = nz;
        __syncthreads();
    }

    if (v < n) g_dis[v * 64 + t] = Z[sub][t] * rsqrtf(s);
}

// ---- stage: compute every nonzero 8x8 block into g_stage (contiguous writes).
//      4 blocks per 256-thread CTA; reverse edge of p is (p +- P/2). ----
__global__ void k_stage(const float* __restrict__ R, const int* __restrict__ E,
                        const float* __restrict__ L1, int P, int n) {
    __shared__ float M1T[4][64], M2[4][64], Di[4][64], Dj[4][64], B[4][64], T[4][64];
    int sub = threadIdx.x >> 6;
    int t   = threadIdx.x & 63;
    int b   = blockIdx.x * 4 + sub;
    bool valid = (b < P + n);
    bool is_edge = valid && (b < P);
    int i = 0, j = 0;
    float sgn = 0.f;

    if (valid) {
        if (is_edge) {
            int2 e = ((const int2*)E)[b];
            i = e.x; j = e.y;
        } else {
            i = j = b - P;
        }
    }

    int r = t >> 3, c = t & 7;
    int g = t & 15, sel = t >> 4;

    if (valid) {
        if (is_edge) {
            int half = P >> 1;
            int rev = (b < half) ? (b + half) : (b - half);
            float l = L1[(size_t)i * n + j];
            sgn = (l > 0.f) ? 1.f : ((l < 0.f) ? -1.f : 0.f);
            if (sel == 0) {
                float4 v = ((const float4*)(R + (size_t)rev * 64))[g];
                int row = g >> 1, c0 = (g & 1) * 4;
                M1T[sub][(c0 + 0) * 8 + row] = v.x;
                M1T[sub][(c0 + 1) * 8 + row] = v.y;
                M1T[sub][(c0 + 2) * 8 + row] = v.z;
                M1T[sub][(c0 + 3) * 8 + row] = v.w;
            } else if (sel == 1) {
                ((float4*)M2[sub])[g] = ((const float4*)(R + (size_t)b * 64))[g];
            } else if (sel == 2) {
                ((float4*)Di[sub])[g] = ((const float4*)(g_dis + (size_t)i * 64))[g];
            } else {
                ((float4*)Dj[sub])[g] = ((const float4*)(g_dis + (size_t)j * 64))[g];
            }
        } else {
            if (sel == 0) {
                ((float4*)B[sub])[g]  = ((const float4*)(g_diag + (size_t)i * 64))[g];
            } else if (sel == 2) {
                ((float4*)Di[sub])[g] = ((const float4*)(g_dis + (size_t)i * 64))[g];
            } else if (sel == 3) {
                ((float4*)Dj[sub])[g] = ((const float4*)(g_dis + (size_t)i * 64))[g];
            }
        }
    }
    __syncthreads();

    if (is_edge) {
        float4 a0 = ((const float4*)(M1T[sub] + r * 8))[0];
        float4 a1 = ((const float4*)(M1T[sub] + r * 8))[1];
        const float* Bc = M2[sub] + c;
        float s = a0.x * Bc[0]  + a0.y * Bc[8]  + a0.z * Bc[16] + a0.w * Bc[24]
                + a1.x * Bc[32] + a1.y * Bc[40] + a1.z * Bc[48] + a1.w * Bc[56];
        B[sub][t] = -sgn * s;
    }
    __syncthreads();
    if (valid) {
        float4 a0 = ((const float4*)(Di[sub] + r * 8))[0];
        float4 a1 = ((const float4*)(Di[sub] + r * 8))[1];
        const float* Bc = B[sub] + c;
        float s = a0.x * Bc[0]  + a0.y * Bc[8]  + a0.z * Bc[16] + a0.w * Bc[24]
                + a1.x * Bc[32] + a1.y * Bc[40] + a1.z * Bc[48] + a1.w * Bc[56];
        T[sub][t] = s;
    }
    __syncthreads();
    if (valid) {
        float4 a0 = ((const float4*)(T[sub] + r * 8))[0];
        float4 a1 = ((const float4*)(T[sub] + r * 8))[1];
        const float* Bc = Dj[sub] + c;
        float s = a0.x * Bc[0]  + a0.y * Bc[8]  + a0.z * Bc[16] + a0.w * Bc[24]
                + a1.x * Bc[32] + a1.y * Bc[40] + a1.z * Bc[48] + a1.w * Bc[56];
        g_stage[(size_t)b * 64 + t] = s;   // contiguous, coalesced
    }
}

// ---- scatter: copy staged blocks into the zeroed output (tiny tail).
//      16 blocks per 256-thread CTA; thread -> one float4 (half a block row). ----
__global__ void k_scatter(const int* __restrict__ E, float* __restrict__ out,
                          int P, int n) {
    int bid = blockIdx.x * 16 + (threadIdx.x >> 4);
    if (bid >= P + n) return;
    int l = threadIdx.x & 15;     // 0..15: (row, half)
    int r = l >> 1, h = l & 1;
    int i, j;
    if (bid < P) { int2 e = ((const int2*)E)[bid]; i = e.x; j = e.y; }
    else         { i = j = bid - P; }
    float4 v = ((const float4*)(g_stage + (size_t)bid * 64))[l];
    size_t nd = (size_t)n * 8;
    ((float4*)(out + ((size_t)i * 8 + r) * nd + (size_t)j * 8))[h] = v;
}

extern "C" void kernel_launch(void* const* d_in, const int* in_sizes, int n_in,
                              void* d_out, int out_size) {
    const float* R  = (const float*)d_in[0];  // (P, 8, 8)
    const int*   E  = (const int*)  d_in[1];  // (P, 2)
    const float* L1 = (const float*)d_in[3];  // (n, n)

    int P = in_sizes[1] / 2;
    int n = (int)(sqrt((double)in_sizes[3]) + 0.5);

    // one-time host-side resources (streams/events are NOT device memory)
    static bool inited = false;
    static cudaStream_t side;
    static cudaEvent_t ev_fork, ev_chain;
    static void* diag_ptr;
    if (!inited) {
        cudaStreamCreateWithFlags(&side, cudaStreamNonBlocking);
        cudaEventCreateWithFlags(&ev_fork, cudaEventDisableTiming);
        cudaEventCreateWithFlags(&ev_chain, cudaEventDisableTiming);
        cudaGetSymbolAddress(&diag_ptr, g_diag);
        inited = true;
    }

    // side stream (forked at t=0): chain + stage — no touches of d_out
    cudaEventRecord(ev_fork, 0);
    cudaStreamWaitEvent(side, ev_fork, 0);
    cudaMemsetAsync(diag_ptr, 0, (size_t)n * 64 * sizeof(float), side);
    k_ftf<<<(P * 64 + 255) / 256, 256, 0, side>>>(R, E, P);
    k_ns<<<(n + 3) / 4, 256, 0, side>>>(n);
    k_stage<<<(P + n + 3) / 4, 256, 0, side>>>(R, E, L1, P, n);
    cudaEventRecord(ev_chain, side);

    // main stream: full TMA bulk-store zero (owns the machine)
    size_t total = (size_t)out_size * sizeof(float);
    size_t per_cta = (size_t)ZPER * ZCHUNK;
    int zgrid = (int)((total + per_cta - 1) / per_cta);
    k_zero_tma<<<zgrid, 128>>>((char*)d_out, total);

    // tiny tail: scatter staged blocks after zero + chain
    cudaStreamWaitEvent(0, ev_chain, 0);
    k_scatter<<<(P + n + 15) / 16, 256>>>(E, (float*)d_out, P, n);
}